// round 14
// baseline (speedup 1.0000x reference)
#include <cuda_runtime.h>
#include <cstdint>

#define T_STEPS    2000
#define LIF_STRIDE 2048
#define N_IN       8192
#define N_OUT      4096

// lif_input stored NEURON-MAJOR: g_lif[n * 2048 + t]
__device__ float g_lif[(size_t)N_OUT * LIF_STRIDE];

// ---------------------------------------------------------------------------
// FFMA2: d = a*b + d per 32-bit half, IEEE fp32 RN — bit-identical to two
// independent scalar FFMA chains.
// ---------------------------------------------------------------------------
__device__ __forceinline__ void ffma2(unsigned long long& d,
                                      unsigned long long a,
                                      unsigned long long b) {
    asm("fma.rn.f32x2 %0, %1, %2, %0;" : "+l"(d) : "l"(a), "l"(b));
}

// ---------------------------------------------------------------------------
// GEMM: lif[n][m] = sum_k A[m,k] * W[n,k], pure fp32, ascending-k FMA chain
// per output element (bit-identical to the reference reduction order).
// Round-8 config (proven best): tile 128(M) x 256(N), BK=16, 256 threads,
// per-thread 8x16 via 64 FFMA2/k, occ 1.
// Change vs round 8: operand fetches use LDS.128 (2 u64 per load) — A dup-
// pairs are naturally adjacent; B pair order permuted so each thread's j,j+1
// pairs are 16B-adjacent. Halves LDS instruction count (80 -> 70 inst/k).
// ---------------------------------------------------------------------------
#define BM 128
#define BN 256
#define BK 16
#define NCHUNKS (N_IN / BK)          // 512
#define STAGE_BYTES 32768            // A 16KB + B 16KB
#define SMEM_TOTAL  (2 * STAGE_BYTES)
#define OFF_B 16384
// B storage permutation: pair p (rows bn+2p, bn+2p+1), logical (tx, j) with
// p = tx + 16j, stored at position s = (j>>1)*32 + tx*2 + (j&1).
__device__ __forceinline__ int b_slot(int p) {
    int tx = p & 15, j = p >> 4;
    return (j >> 1) * 32 + tx * 2 + (j & 1);
}

struct LdRegs { float4 a[2]; float4 b[4]; };

__device__ __forceinline__ void ldg_chunk(const float* __restrict__ A,
                                          const float* __restrict__ B,
                                          int bm, int bn, int k0, int tid,
                                          LdRegs& r) {
    // A: row = tid/2 (0..127), k-offset = (tid&1)*8
    int ar = bm + (tid >> 1); if (ar > T_STEPS - 1) ar = T_STEPS - 1;
    int ko = (tid & 1) * 8;
    const float* ap = &A[(size_t)ar * N_IN + k0 + ko];
    r.a[0] = *reinterpret_cast<const float4*>(ap);
    r.a[1] = *reinterpret_cast<const float4*>(ap + 4);
    // B: pair p = tid/2 (0..127)
    int p = tid >> 1;
    const float* bp0 = &B[(size_t)(bn + 2 * p) * N_IN + k0 + ko];
    const float* bp1 = &B[(size_t)(bn + 2 * p + 1) * N_IN + k0 + ko];
    r.b[0] = *reinterpret_cast<const float4*>(bp0);
    r.b[1] = *reinterpret_cast<const float4*>(bp0 + 4);
    r.b[2] = *reinterpret_cast<const float4*>(bp1);
    r.b[3] = *reinterpret_cast<const float4*>(bp1 + 4);
}

__device__ __forceinline__ void sts_chunk(char* stage, int tid, const LdRegs& r) {
    int row = tid >> 1;              // A row / B pair index
    int ko  = (tid & 1) * 8;
    int bs  = b_slot(row);           // permuted B position
    const float* av  = (const float*)&r.a[0];
    const float* bv0 = (const float*)&r.b[0];
    const float* bv1 = (const float*)&r.b[2];
    #pragma unroll
    for (int e = 0; e < 8; e++) {
        int k = ko + e;
        float a = av[e];
        *reinterpret_cast<float2*>(stage + (size_t)k * 1024 + row * 8) =
            make_float2(a, a);
        *reinterpret_cast<float2*>(stage + OFF_B + (size_t)k * 1024 + bs * 8) =
            make_float2(bv0[e], bv1[e]);
    }
}

__global__ __launch_bounds__(256, 1)
void gemm_ffma2(const float* __restrict__ A,   // [2000, 8192]
                const float* __restrict__ B)   // [4096, 8192]
{
    extern __shared__ char smem[];
    const int tid = threadIdx.x;
    const int tx  = tid & 15;        // n group
    const int ty  = tid >> 4;        // m group
    const int bm  = blockIdx.y * BM;
    const int bn  = blockIdx.x * BN;

    unsigned long long acc[8][8];    // [m][n-pair], halves = (n_even, n_odd)
    #pragma unroll
    for (int i = 0; i < 8; i++)
        #pragma unroll
        for (int j = 0; j < 8; j++) acc[i][j] = 0ull;

    LdRegs regs;
    ldg_chunk(A, B, bm, bn, 0, tid, regs);

    for (int c = 0; c < NCHUNKS; c++) {
        char* stage = smem + (c & 1) * STAGE_BYTES;
        sts_chunk(stage, tid, regs);
        __syncthreads();
        if (c + 1 < NCHUNKS) ldg_chunk(A, B, bm, bn, (c + 1) * BK, tid, regs);

        const char* sA = stage;
        const char* sB = stage + OFF_B;
        #pragma unroll
        for (int k = 0; k < BK; k++) {
            unsigned long long ra[8], bb[8];
            // A: 4x LDS.128 — dup-pairs for m, m+1 are adjacent
            #pragma unroll
            for (int i = 0; i < 8; i += 2) {
                ulonglong2 v = *reinterpret_cast<const ulonglong2*>(
                    sA + (size_t)k * 1024 + (ty * 8 + i) * 8);
                ra[i] = v.x; ra[i + 1] = v.y;
            }
            // B: 4x LDS.128 — permuted storage puts (tx,j),(tx,j+1) adjacent
            #pragma unroll
            for (int j = 0; j < 8; j += 2) {
                ulonglong2 v = *reinterpret_cast<const ulonglong2*>(
                    sB + (size_t)k * 1024 + ((j >> 1) * 32 + tx * 2) * 8);
                bb[j] = v.x; bb[j + 1] = v.y;
            }
            #pragma unroll
            for (int i = 0; i < 8; i++)
                #pragma unroll
                for (int j = 0; j < 8; j++)
                    ffma2(acc[i][j], ra[i], bb[j]);
        }
        // Double-buffer safety: next iteration's sts targets the other stage,
        // reached only after this barrier, which follows all reads of it.
    }

    // Epilogue: scatter transposed into neuron-major g_lif[n][m]
    #pragma unroll
    for (int i = 0; i < 8; i++) {
        int m = bm + ty * 8 + i;
        if (m < T_STEPS) {
            #pragma unroll
            for (int j = 0; j < 8; j++) {
                int n0 = bn + 2 * (tx + 16 * j);
                float lo = __uint_as_float((uint32_t)(acc[i][j] & 0xFFFFFFFFull));
                float hi = __uint_as_float((uint32_t)(acc[i][j] >> 32));
                g_lif[(size_t)n0 * LIF_STRIDE + m]       = lo;
                g_lif[(size_t)(n0 + 1) * LIF_STRIDE + m] = hi;
            }
        }
    }
}

// ---------------------------------------------------------------------------
// LIF scan: neuron-major streaming input, float4 loads, 8-block prefetch.
// grid 16 x block 256 -> 2 warps per SMSP so instruction latencies are
// covered by the partner warp (was 1 warp/SMSP = fully exposed latency).
// Select-based inner loop, bit-exact vs reference.
// ---------------------------------------------------------------------------
__global__ __launch_bounds__(256)
void lif_scan(const float* __restrict__ vth_p,
              const float* __restrict__ vrest_p,
              const float* __restrict__ vreset_p,
              const float* __restrict__ tref_p,
              const float* __restrict__ tau_p,
              float* __restrict__ out)
{
    const int j = blockIdx.x * 256 + threadIdx.x;

    const float Vth    = vth_p[j];
    const float Vrest  = vrest_p[j];
    const float Vreset = vreset_p[j];
    const float Tref   = tref_p[j];
    const float ktau   = __fmul_rn(0.001f, tau_p[j]);
    const float DT     = 0.001f;

    float v = Vrest, refrac = 0.f;
    out[j] = 0.f;   // t = 0 row

    const float* __restrict__ row = g_lif + (size_t)j * LIF_STRIDE;
    const int NBLK = T_STEPS / 8;   // 250

    float4 pf[16];
    #pragma unroll
    for (int b = 0; b < 8; b++) {
        pf[2 * b]     = *reinterpret_cast<const float4*>(row + 8 * b);
        pf[2 * b + 1] = *reinterpret_cast<const float4*>(row + 8 * b + 4);
    }

    for (int b = 0; b < NBLK; b++) {
        int slot = (b & 7) * 2;
        float vals[8];
        vals[0] = pf[slot].x;   vals[1] = pf[slot].y;
        vals[2] = pf[slot].z;   vals[3] = pf[slot].w;
        vals[4] = pf[slot+1].x; vals[5] = pf[slot+1].y;
        vals[6] = pf[slot+1].z; vals[7] = pf[slot+1].w;
        if (b + 8 < NBLK) {
            pf[slot]     = *reinterpret_cast<const float4*>(row + 8 * (b + 8));
            pf[slot + 1] = *reinterpret_cast<const float4*>(row + 8 * (b + 8) + 4);
        }
        #pragma unroll
        for (int u = 0; u < 8; u++) {
            int t = 8 * b + u;
            if (t == 0) continue;
            float inp = vals[u];
            // leak
            v = __fsub_rn(v, __fmul_rn(ktau, __fsub_rn(v, Vrest)));
            // gate on refractory state (captured BEFORE countdown)
            unsigned rb = __float_as_uint(refrac);
            float vadd  = __fadd_rn(v, inp);
            v = (rb == 0u) ? vadd : v;
            // refractory countdown
            float rdec = __fsub_rn(refrac, DT);
            refrac = (rb == 0u) ? 0.f : rdec;
            // spike + reset (sign-int test; d can never be -0.0)
            float d  = __fsub_rn(v, Vth);
            int   ds = __float_as_int(d);
            float spike = (ds >= 0) ? 1.f : 0.f;
            v      = (ds >= 0) ? Vreset : v;
            refrac = (ds >= 0) ? Tref : refrac;
            out[(size_t)t * N_OUT + j] = spike;
        }
    }
}

// ===========================================================================
extern "C" void kernel_launch(void* const* d_in, const int* in_sizes, int n_in,
                              void* d_out, int out_size)
{
    const float* x      = (const float*)d_in[0];
    const float* weight = (const float*)d_in[1];
    const float* vth    = (const float*)d_in[2];
    const float* vrest  = (const float*)d_in[3];
    const float* vreset = (const float*)d_in[4];
    const float* tref   = (const float*)d_in[5];
    const float* tau    = (const float*)d_in[6];
    float* out = (float*)d_out;

    cudaFuncSetAttribute(gemm_ffma2,
                         cudaFuncAttributeMaxDynamicSharedMemorySize, SMEM_TOTAL);

    dim3 ggrid(N_OUT / BN, (T_STEPS + BM - 1) / BM);   // 16 x 16 = 256 CTAs
    gemm_ffma2<<<ggrid, 256, SMEM_TOTAL>>>(x, weight);

    lif_scan<<<N_OUT / 256, 256>>>(vth, vrest, vreset, tref, tau, out);
}

// round 15
// speedup vs baseline: 1.0120x; 1.0120x over previous
#include <cuda_runtime.h>
#include <cstdint>

#define T_STEPS    2000
#define LIF_STRIDE 2048
#define N_IN       8192
#define N_OUT      4096

// lif_input stored NEURON-MAJOR: g_lif[n * 2048 + t]
__device__ float g_lif[(size_t)N_OUT * LIF_STRIDE];

// ---------------------------------------------------------------------------
// FFMA2: d = a*b + d per 32-bit half, IEEE fp32 RN — bit-identical to two
// independent scalar FFMA chains.
// ---------------------------------------------------------------------------
__device__ __forceinline__ void ffma2(unsigned long long& d,
                                      unsigned long long a,
                                      unsigned long long b) {
    asm("fma.rn.f32x2 %0, %1, %2, %0;" : "+l"(d) : "l"(a), "l"(b));
}

// ---------------------------------------------------------------------------
// GEMM (round-8 config, best measured): lif[n][m] = sum_k A[m,k] * W[n,k],
// pure fp32, ascending-k FMA chain per output element (bit-identical to the
// reference reduction order). Tile 128(M) x 256(N), BK=16, 256 threads,
// per-thread 8x16 via 64 FFMA2/k. smem: A dup-pairs, B natural pairs.
// ---------------------------------------------------------------------------
#define BM 128
#define BN 256
#define BK 16
#define NCHUNKS (N_IN / BK)          // 512
#define STAGE_BYTES 32768            // A 16KB + B 16KB
#define SMEM_TOTAL  (2 * STAGE_BYTES)
#define OFF_B 16384

struct LdRegs { float4 a[2]; float4 b[4]; };

__device__ __forceinline__ void ldg_chunk(const float* __restrict__ A,
                                          const float* __restrict__ B,
                                          int bm, int bn, int k0, int tid,
                                          LdRegs& r) {
    int ar = bm + (tid >> 1); if (ar > T_STEPS - 1) ar = T_STEPS - 1;
    int ko = (tid & 1) * 8;
    const float* ap = &A[(size_t)ar * N_IN + k0 + ko];
    r.a[0] = *reinterpret_cast<const float4*>(ap);
    r.a[1] = *reinterpret_cast<const float4*>(ap + 4);
    int p = tid >> 1;
    const float* bp0 = &B[(size_t)(bn + 2 * p) * N_IN + k0 + ko];
    const float* bp1 = &B[(size_t)(bn + 2 * p + 1) * N_IN + k0 + ko];
    r.b[0] = *reinterpret_cast<const float4*>(bp0);
    r.b[1] = *reinterpret_cast<const float4*>(bp0 + 4);
    r.b[2] = *reinterpret_cast<const float4*>(bp1);
    r.b[3] = *reinterpret_cast<const float4*>(bp1 + 4);
}

__device__ __forceinline__ void sts_chunk(char* stage, int tid, const LdRegs& r) {
    int row = tid >> 1;
    int ko  = (tid & 1) * 8;
    const float* av  = (const float*)&r.a[0];
    const float* bv0 = (const float*)&r.b[0];
    const float* bv1 = (const float*)&r.b[2];
    #pragma unroll
    for (int e = 0; e < 8; e++) {
        int k = ko + e;
        float a = av[e];
        *reinterpret_cast<float2*>(stage + (size_t)k * 1024 + row * 8) =
            make_float2(a, a);
        *reinterpret_cast<float2*>(stage + OFF_B + (size_t)k * 1024 + row * 8) =
            make_float2(bv0[e], bv1[e]);
    }
}

__global__ __launch_bounds__(256, 1)
void gemm_ffma2(const float* __restrict__ A,   // [2000, 8192]
                const float* __restrict__ B)   // [4096, 8192]
{
    extern __shared__ char smem[];
    const int tid = threadIdx.x;
    const int tx  = tid & 15;        // n group
    const int ty  = tid >> 4;        // m group
    const int bm  = blockIdx.y * BM;
    const int bn  = blockIdx.x * BN;

    unsigned long long acc[8][8];    // [m][n-pair], halves = (n_even, n_odd)
    #pragma unroll
    for (int i = 0; i < 8; i++)
        #pragma unroll
        for (int j = 0; j < 8; j++) acc[i][j] = 0ull;

    LdRegs regs;
    ldg_chunk(A, B, bm, bn, 0, tid, regs);

    for (int c = 0; c < NCHUNKS; c++) {
        char* stage = smem + (c & 1) * STAGE_BYTES;
        sts_chunk(stage, tid, regs);
        __syncthreads();
        if (c + 1 < NCHUNKS) ldg_chunk(A, B, bm, bn, (c + 1) * BK, tid, regs);

        const char* sA = stage;
        const char* sB = stage + OFF_B;
        #pragma unroll
        for (int k = 0; k < BK; k++) {
            unsigned long long ra[8], bb[8];
            #pragma unroll
            for (int i = 0; i < 8; i++)
                ra[i] = *reinterpret_cast<const unsigned long long*>(
                    sA + (size_t)k * 1024 + (ty * 8 + i) * 8);
            #pragma unroll
            for (int j = 0; j < 8; j++)
                bb[j] = *reinterpret_cast<const unsigned long long*>(
                    sB + (size_t)k * 1024 + (tx + 16 * j) * 8);
            #pragma unroll
            for (int i = 0; i < 8; i++)
                #pragma unroll
                for (int j = 0; j < 8; j++)
                    ffma2(acc[i][j], ra[i], bb[j]);
        }
        // Double-buffer safety: next iteration's sts targets the other stage,
        // reached only after this barrier, which follows all reads of it.
    }

    // Epilogue: scatter transposed into neuron-major g_lif[n][m]
    #pragma unroll
    for (int i = 0; i < 8; i++) {
        int m = bm + ty * 8 + i;
        if (m < T_STEPS) {
            #pragma unroll
            for (int j = 0; j < 8; j++) {
                int n0 = bn + 2 * (tx + 16 * j);
                float lo = __uint_as_float((uint32_t)(acc[i][j] & 0xFFFFFFFFull));
                float hi = __uint_as_float((uint32_t)(acc[i][j] >> 32));
                g_lif[(size_t)n0 * LIF_STRIDE + m]       = lo;
                g_lif[(size_t)(n0 + 1) * LIF_STRIDE + m] = hi;
            }
        }
    }
}

// ---------------------------------------------------------------------------
// LIF scan, ILP-2: each thread owns TWO neurons (j, j+2048); the two
// independent recurrence chains interleave so each chain's latency is hidden
// by the other's instructions. 64 CTAs x 32 threads. 4-block prefetch per
// neuron. Select-based inner loop, bit-exact vs reference.
// ---------------------------------------------------------------------------
__global__ __launch_bounds__(32)
void lif_scan(const float* __restrict__ vth_p,
              const float* __restrict__ vrest_p,
              const float* __restrict__ vreset_p,
              const float* __restrict__ tref_p,
              const float* __restrict__ tau_p,
              float* __restrict__ out)
{
    const int j0 = blockIdx.x * 32 + threadIdx.x;   // 0..2047
    const int j1 = j0 + 2048;

    const float Vth0    = vth_p[j0],    Vth1    = vth_p[j1];
    const float Vrest0  = vrest_p[j0],  Vrest1  = vrest_p[j1];
    const float Vreset0 = vreset_p[j0], Vreset1 = vreset_p[j1];
    const float Tref0   = tref_p[j0],   Tref1   = tref_p[j1];
    const float ktau0   = __fmul_rn(0.001f, tau_p[j0]);
    const float ktau1   = __fmul_rn(0.001f, tau_p[j1]);
    const float DT      = 0.001f;

    float v0 = Vrest0, refrac0 = 0.f;
    float v1 = Vrest1, refrac1 = 0.f;
    out[j0] = 0.f;
    out[j1] = 0.f;

    const float* __restrict__ row0 = g_lif + (size_t)j0 * LIF_STRIDE;
    const float* __restrict__ row1 = g_lif + (size_t)j1 * LIF_STRIDE;
    const int NBLK = T_STEPS / 8;   // 250

    float4 pf0[8], pf1[8];          // 4 blocks x 2 float4, per neuron
    #pragma unroll
    for (int b = 0; b < 4; b++) {
        pf0[2 * b]     = *reinterpret_cast<const float4*>(row0 + 8 * b);
        pf0[2 * b + 1] = *reinterpret_cast<const float4*>(row0 + 8 * b + 4);
        pf1[2 * b]     = *reinterpret_cast<const float4*>(row1 + 8 * b);
        pf1[2 * b + 1] = *reinterpret_cast<const float4*>(row1 + 8 * b + 4);
    }

    for (int b = 0; b < NBLK; b++) {
        int slot = (b & 3) * 2;
        float va_[8], vb_[8];
        va_[0] = pf0[slot].x;   va_[1] = pf0[slot].y;
        va_[2] = pf0[slot].z;   va_[3] = pf0[slot].w;
        va_[4] = pf0[slot+1].x; va_[5] = pf0[slot+1].y;
        va_[6] = pf0[slot+1].z; va_[7] = pf0[slot+1].w;
        vb_[0] = pf1[slot].x;   vb_[1] = pf1[slot].y;
        vb_[2] = pf1[slot].z;   vb_[3] = pf1[slot].w;
        vb_[4] = pf1[slot+1].x; vb_[5] = pf1[slot+1].y;
        vb_[6] = pf1[slot+1].z; vb_[7] = pf1[slot+1].w;
        if (b + 4 < NBLK) {
            pf0[slot]     = *reinterpret_cast<const float4*>(row0 + 8 * (b + 4));
            pf0[slot + 1] = *reinterpret_cast<const float4*>(row0 + 8 * (b + 4) + 4);
            pf1[slot]     = *reinterpret_cast<const float4*>(row1 + 8 * (b + 4));
            pf1[slot + 1] = *reinterpret_cast<const float4*>(row1 + 8 * (b + 4) + 4);
        }
        #pragma unroll
        for (int u = 0; u < 8; u++) {
            int t = 8 * b + u;
            if (t == 0) continue;
            // --- chain 0 ---
            float inp0 = va_[u];
            v0 = __fsub_rn(v0, __fmul_rn(ktau0, __fsub_rn(v0, Vrest0)));
            unsigned rb0 = __float_as_uint(refrac0);
            float vad0  = __fadd_rn(v0, inp0);
            v0 = (rb0 == 0u) ? vad0 : v0;
            float rdec0 = __fsub_rn(refrac0, DT);
            refrac0 = (rb0 == 0u) ? 0.f : rdec0;
            float d0  = __fsub_rn(v0, Vth0);
            int   ds0 = __float_as_int(d0);
            float spike0 = (ds0 >= 0) ? 1.f : 0.f;
            v0      = (ds0 >= 0) ? Vreset0 : v0;
            refrac0 = (ds0 >= 0) ? Tref0 : refrac0;
            // --- chain 1 (independent; fills chain 0's latency slots) ---
            float inp1 = vb_[u];
            v1 = __fsub_rn(v1, __fmul_rn(ktau1, __fsub_rn(v1, Vrest1)));
            unsigned rb1 = __float_as_uint(refrac1);
            float vad1  = __fadd_rn(v1, inp1);
            v1 = (rb1 == 0u) ? vad1 : v1;
            float rdec1 = __fsub_rn(refrac1, DT);
            refrac1 = (rb1 == 0u) ? 0.f : rdec1;
            float d1  = __fsub_rn(v1, Vth1);
            int   ds1 = __float_as_int(d1);
            float spike1 = (ds1 >= 0) ? 1.f : 0.f;
            v1      = (ds1 >= 0) ? Vreset1 : v1;
            refrac1 = (ds1 >= 0) ? Tref1 : refrac1;
            // stores (off the dependence chains)
            out[(size_t)t * N_OUT + j0] = spike0;
            out[(size_t)t * N_OUT + j1] = spike1;
        }
    }
}

// ===========================================================================
extern "C" void kernel_launch(void* const* d_in, const int* in_sizes, int n_in,
                              void* d_out, int out_size)
{
    const float* x      = (const float*)d_in[0];
    const float* weight = (const float*)d_in[1];
    const float* vth    = (const float*)d_in[2];
    const float* vrest  = (const float*)d_in[3];
    const float* vreset = (const float*)d_in[4];
    const float* tref   = (const float*)d_in[5];
    const float* tau    = (const float*)d_in[6];
    float* out = (float*)d_out;

    cudaFuncSetAttribute(gemm_ffma2,
                         cudaFuncAttributeMaxDynamicSharedMemorySize, SMEM_TOTAL);

    dim3 ggrid(N_OUT / BN, (T_STEPS + BM - 1) / BM);   // 16 x 16 = 256 CTAs
    gemm_ffma2<<<ggrid, 256, SMEM_TOTAL>>>(x, weight);

    lif_scan<<<2048 / 32, 32>>>(vth, vrest, vreset, tref, tau, out);
}